// round 13
// baseline (speedup 1.0000x reference)
#include <cuda_runtime.h>
#include <cuda_bf16.h>
#include <cuda_fp16.h>
#include <math.h>
#include <stdint.h>

// Problem constants
#define BATCH 4
#define SLEN  2048
#define EMB   1024
#define QKVF  3072

// ---------------------------------------------------------------------------
// Device scratch (allocation-free rule: __device__ globals)
// ---------------------------------------------------------------------------
__device__ __align__(256) __half g_Xf [(size_t)BATCH*SLEN*EMB];   // X single fp16
__device__ __align__(256) __half g_Wqh[(size_t)QKVF*EMB];         // W_qkv fp16 hi
__device__ __align__(256) __half g_Wql[(size_t)QKVF*EMB];         // W_qkv fp16 lo
__device__ __align__(256) __half g_Wof[(size_t)EMB*EMB];          // W_out single fp16
__device__ __align__(256) __half g_qf [(size_t)BATCH*SLEN*EMB];   // q single fp16
__device__ __align__(256) __half g_kf [(size_t)BATCH*SLEN*EMB];   // k single fp16
__device__ __align__(256) __half g_vtf[(size_t)BATCH*EMB*SLEN];   // V^T single fp16
__device__ __align__(256) float  g_att[(size_t)BATCH*SLEN*SLEN];
__device__ __align__(256) __half g_athf[(size_t)BATCH*SLEN*SLEN]; // att single fp16
__device__ __align__(256) __half g_cfh[(size_t)BATCH*SLEN*EMB];   // ctx fp16 hi
__device__ __align__(256) __half g_cfl[(size_t)BATCH*SLEN*EMB];   // ctx fp16 lo

// ---------------------------------------------------------------------------
// PTX helpers (sm_80+ only — tcgen05 rejected by compute_103 PTX target)
// ---------------------------------------------------------------------------
__device__ __forceinline__ uint32_t smem_u32(const void* p) {
    uint32_t a;
    asm("{ .reg .u64 t; cvta.to.shared.u64 t, %1; cvt.u32.u64 %0, t; }"
        : "=r"(a) : "l"(p));
    return a;
}
#define CP16(d, s)   asm volatile("cp.async.cg.shared.global [%0], [%1], 16;" :: "r"(d), "l"(s))
#define CP_COMMIT()  asm volatile("cp.async.commit_group;" ::: "memory")
#define CP_WAIT0()   asm volatile("cp.async.wait_group 0;" ::: "memory")

__device__ __forceinline__ void ldsm4(uint32_t* r, uint32_t addr) {
    asm volatile("ldmatrix.sync.aligned.m8n8.x4.shared.b16 {%0,%1,%2,%3}, [%4];"
        : "=r"(r[0]), "=r"(r[1]), "=r"(r[2]), "=r"(r[3]) : "r"(addr));
}
__device__ __forceinline__ void hmma16816(float* d, const uint32_t* a, const uint32_t* b) {
    asm volatile("mma.sync.aligned.m16n8k16.row.col.f32.f16.f16.f32 "
        "{%0,%1,%2,%3}, {%4,%5,%6,%7}, {%8,%9}, {%0,%1,%2,%3};"
        : "+f"(d[0]), "+f"(d[1]), "+f"(d[2]), "+f"(d[3])
        : "r"(a[0]), "r"(a[1]), "r"(a[2]), "r"(a[3]), "r"(b[0]), "r"(b[1]));
}

// ---- fp16 tiling: CTA 128x128, BK=64, 8 warps (2x4), 2 CTAs/SM ----
#define HROWB   144
#define HTILE   (128 * HROWB)        // 18432 B
#define HG_SMEM3 (2 * 3 * HTILE + 128)   // split modes: 110720 B
#define HG_SMEM2 (2 * 2 * HTILE + 128)   // pure  modes:  73856 B

// ===========================================================================
// hgemm:  D[m,n] = alpha*sum_k A[m,k]B[n,k] (+bias)
// MODE 0 (qkv, 2-MMA):   A = Sg (X single), B = S0/S1 (Wq hi/lo); bias;
//                        emit q fp16 / k fp16 / V^T fp16 (transposed).
// MODE 1 (scores, pure): A = Sg (q), B = S0 (k); fp32 att out.
// MODE 2 (ctx, pure):    A = Sg (att), B = S0 (V^T); ctx fp16 hi/lo out.
// MODE 3 (proj, 2-MMA):  A = S0/S1 (ctx hi/lo), B = Sg (W_out); bias; fp32 out.
// ===========================================================================
template<int MODE>
__global__ void __launch_bounds__(256, 2)
hgemm_k(const __half* __restrict__ S0, const __half* __restrict__ S1,
        const __half* __restrict__ Sg,
        size_t sS, int ldS, size_t sG, int ldG, int K, float alpha,
        float* __restrict__ outF, size_t sF, int ldF,
        __half* __restrict__ o0, __half* __restrict__ o1,
        __half* __restrict__ o3,
        const float* __restrict__ bias)
{
    extern __shared__ char dsm[];
    const uint32_t sb0 = smem_u32(dsm);
    const uint32_t SB  = (sb0 + 127u) & ~127u;
    float* stg = (float*)(dsm + (SB - sb0));

    const int tid  = threadIdx.x;
    const int wid  = tid >> 5, lane = tid & 31;
    const int wm   = wid >> 2, wn = wid & 3;    // warp 64x32
    const int bx = blockIdx.x, by = blockIdx.y, z = blockIdx.z;

    constexpr bool PURE    = (MODE == 1 || MODE == 2);
    constexpr bool SPLIT_A = (MODE == 3);
    constexpr int  NTILES  = PURE ? 2 : 3;
    constexpr uint32_t HSTAGE = (uint32_t)NTILES * HTILE;

    const int splitRow  = (SPLIT_A ? by : bx) * 128;   // rows of S0/S1
    const int singleRow = (SPLIT_A ? bx : by) * 128;   // rows of Sg
    const char* b0 = (const char*)(S0 + (size_t)z * sS + (size_t)splitRow * ldS);
    const char* b1 = PURE ? nullptr
                   : (const char*)(S1 + (size_t)z * sS + (size_t)splitRow * ldS);
    const char* bg = (const char*)(Sg + (size_t)z * sG + (size_t)singleRow * ldG);
    const size_t strS = (size_t)ldS * 2, strG = (size_t)ldG * 2;

    auto load_chunk = [&](int c, int s) {
        const uint32_t stb = SB + (uint32_t)s * HSTAGE;
        #pragma unroll
        for (int i = 0; i < NTILES * 4; i++) {
            const int id = i * 256 + tid;
            const int t  = id >> 10;            // tile 0..NTILES-1
            const int u  = id & 1023;
            const int r  = u >> 3;
            const int c16 = u & 7;
            const char* base; size_t str;
            if (t == 0)              { base = b0; str = strS; }
            else if (PURE || t == 2) { base = bg; str = strG; }
            else                     { base = b1; str = strS; }
            const char* src = base + (size_t)r * str + (size_t)c * 128 + (size_t)c16 * 16;
            const uint32_t dst = stb + (uint32_t)t * HTILE + (uint32_t)(r * HROWB + c16 * 16);
            CP16(dst, src);
        }
        CP_COMMIT();
    };

    float d[4][4][4];
    #pragma unroll
    for (int a = 0; a < 4; a++)
        #pragma unroll
        for (int b = 0; b < 4; b++)
            #pragma unroll
            for (int e = 0; e < 4; e++) d[a][b][e] = 0.0f;

    const int NC = K >> 6;
    load_chunk(0, 0);

    const uint32_t offA = (uint32_t)((wm * 64 + (lane & 7) + ((lane >> 3) & 1) * 8) * HROWB
                                     + ((lane >> 4) & 1) * 16);
    const uint32_t offB = (uint32_t)((wn * 32 + ((lane >> 4) & 1) * 8 + (lane & 7)) * HROWB
                                     + ((lane >> 3) & 1) * 16);

    for (int c = 0; c < NC; c++) {
        CP_WAIT0();
        __syncthreads();
        const int s = c & 1;
        if (c + 1 < NC) load_chunk(c + 1, s ^ 1);

        const uint32_t stb = SB + (uint32_t)s * HSTAGE;

        if (PURE) {          // single x single, 1 MMA
            const uint32_t B_s = stb, A_s = stb + HTILE;
            #pragma unroll
            for (int kk = 0; kk < 4; kk++) {
                uint32_t bq[8];
                ldsm4(&bq[0], B_s + offB + (uint32_t)(kk * 32));
                ldsm4(&bq[4], B_s + offB + (uint32_t)(16 * HROWB + kk * 32));
                #pragma unroll
                for (int mt = 0; mt < 4; mt++) {
                    uint32_t a[4];
                    ldsm4(a, A_s + offA + (uint32_t)(mt * 16 * HROWB + kk * 32));
                    #pragma unroll
                    for (int nt = 0; nt < 4; nt++)
                        hmma16816(d[mt][nt], a, &bq[nt * 2]);
                }
            }
        } else if (!SPLIT_A) {   // split B (hi/lo), single A — 2 MMAs
            const uint32_t Bh_s = stb, Bl_s = stb + HTILE, A_s = stb + 2 * HTILE;
            #pragma unroll
            for (int kk = 0; kk < 4; kk++) {
                uint32_t p0[8], p1[8];
                ldsm4(&p0[0], Bh_s + offB + (uint32_t)(kk * 32));
                ldsm4(&p0[4], Bh_s + offB + (uint32_t)(16 * HROWB + kk * 32));
                ldsm4(&p1[0], Bl_s + offB + (uint32_t)(kk * 32));
                ldsm4(&p1[4], Bl_s + offB + (uint32_t)(16 * HROWB + kk * 32));
                #pragma unroll
                for (int mt = 0; mt < 4; mt++) {
                    uint32_t a[4];
                    ldsm4(a, A_s + offA + (uint32_t)(mt * 16 * HROWB + kk * 32));
                    #pragma unroll
                    for (int nt = 0; nt < 4; nt++) {
                        hmma16816(d[mt][nt], a, &p0[nt * 2]);
                        hmma16816(d[mt][nt], a, &p1[nt * 2]);
                    }
                }
            }
        } else {             // split A (hi/lo), single B — 2 MMAs
            const uint32_t Ah_s = stb, Al_s = stb + HTILE, B_s = stb + 2 * HTILE;
            #pragma unroll
            for (int kk = 0; kk < 4; kk++) {
                uint32_t bq[8];
                ldsm4(&bq[0], B_s + offB + (uint32_t)(kk * 32));
                ldsm4(&bq[4], B_s + offB + (uint32_t)(16 * HROWB + kk * 32));
                #pragma unroll
                for (int mt = 0; mt < 4; mt++) {
                    uint32_t ah[4], al[4];
                    const uint32_t o = (uint32_t)(mt * 16 * HROWB + kk * 32);
                    ldsm4(ah, Ah_s + offA + o);
                    ldsm4(al, Al_s + offA + o);
                    #pragma unroll
                    for (int nt = 0; nt < 4; nt++) {
                        hmma16816(d[mt][nt], ah, &bq[nt * 2]);
                        hmma16816(d[mt][nt], al, &bq[nt * 2]);
                    }
                }
            }
        }
    }
    __syncthreads();

    // ---- accumulators -> smem staging (alpha, optional bias) ----
    #pragma unroll
    for (int mt = 0; mt < 4; mt++) {
        #pragma unroll
        for (int nt = 0; nt < 4; nt++) {
            const int r0 = wm * 64 + mt * 16 + (lane >> 2);
            const int c0 = wn * 32 + nt * 8 + (lane & 3) * 2;
            #pragma unroll
            for (int h = 0; h < 2; h++) {
                float v0 = d[mt][nt][h * 2 + 0] * alpha;
                float v1 = d[mt][nt][h * 2 + 1] * alpha;
                if (MODE == 0 || MODE == 3) {
                    v0 += bias[bx * 128 + c0];
                    v1 += bias[bx * 128 + c0 + 1];
                }
                *(float2*)&stg[(r0 + h * 8) * 132 + c0] = make_float2(v0, v1);
            }
        }
    }
    __syncthreads();

    // ---- MODE-specific writers ----
    if (MODE == 1 || MODE == 3) {
        const int row = tid >> 1, h = tid & 1;
        float* dst = outF + (size_t)z * sF + ((size_t)by * 128 + row) * ldF
                   + (size_t)bx * 128 + h * 64;
        #pragma unroll
        for (int q = 0; q < 16; q++) {
            float4 v;
            v.x = stg[row * 132 + h * 64 + q * 4 + 0];
            v.y = stg[row * 132 + h * 64 + q * 4 + 1];
            v.z = stg[row * 132 + h * 64 + q * 4 + 2];
            v.w = stg[row * 132 + h * 64 + q * 4 + 3];
            ((float4*)dst)[q] = v;
        }
    } else if (MODE == 2) {
        // ctx -> fp16 hi/lo (row-major): o0 = hi, o1 = lo
        #pragma unroll 1
        for (int cb = 0; cb < 4; cb++) {
            #pragma unroll 1
            for (int it = 0; it < 2; it++) {
                const int row = it * 64 + (tid >> 2);
                const int qq  = tid & 3;
                const int col = cb * 32 + qq * 8;
                const size_t rg = (size_t)z * SLEN + (size_t)by * 128 + row;
                union { __half h[8]; uint4 v; } Uh, Ul;
                #pragma unroll
                for (int i = 0; i < 8; i++) {
                    float v = stg[row * 132 + col + i];
                    __half hi = __float2half(v);
                    Uh.h[i] = hi;
                    Ul.h[i] = __float2half(v - __half2float(hi));
                }
                const size_t off = rg * 1024 + bx * 128 + col;
                *(uint4*)(o0 + off) = Uh.v;
                *(uint4*)(o1 + off) = Ul.v;
            }
        }
    } else if (MODE == 0 && bx < 16) {      // q (bx<8 -> o0) or k (bx<16 -> o1), single fp16
        __half* O = (bx < 8) ? o0 : o1;
        const int cbase = (bx & 7) * 128;
        #pragma unroll 1
        for (int cb = 0; cb < 4; cb++) {
            #pragma unroll 1
            for (int it = 0; it < 2; it++) {
                const int row = it * 64 + (tid >> 2);
                const int qq  = tid & 3;
                const int col = cb * 32 + qq * 8;
                const size_t rg = (size_t)by * 128 + row;
                union { __half h[8]; uint4 v; } U;
                #pragma unroll
                for (int i = 0; i < 8; i++)
                    U.h[i] = __float2half(stg[row * 132 + col + i]);
                *(uint4*)(O + rg * 1024 + cbase + col) = U.v;
            }
        }
    } else if (MODE == 0) {                 // V^T single fp16, transposed (o3)
        const int j  = tid >> 3;
        const int rs = tid & 7;
        const int bidx = by >> 4;
        const int s0 = (by * 128) & 2047;
        #pragma unroll 1
        for (int cb = 0; cb < 4; cb++) {
            const int col = cb * 32 + j;
            const int colE = (bx - 16) * 128 + col;
            union { __half h[16]; uint4 v[2]; } U;
            #pragma unroll
            for (int i = 0; i < 16; i++)
                U.h[i] = __float2half(stg[(rs * 16 + i) * 132 + col]);
            const size_t off = ((size_t)bidx * 1024 + colE) * 2048 + s0 + rs * 16;
            *(uint4*)(o3 + off)     = U.v[0];
            *(uint4*)(o3 + off + 8) = U.v[1];
        }
    }
}

// ---------------------------------------------------------------------------
// Input conversion: X -> fp16 single, W_qkv -> fp16 hi/lo, W_out -> fp16 single
// ---------------------------------------------------------------------------
__global__ void conv_all(const float4* __restrict__ X,  __half* __restrict__ Xf, int n1,
                         const float4* __restrict__ Wq, __half* __restrict__ Wqh,
                         __half* __restrict__ Wql, int n2,
                         const float4* __restrict__ Wo, __half* __restrict__ Wof, int n3)
{
    int i = blockIdx.x * 256 + threadIdx.x;
    if (i < n1) {
        const float4 v = X[i];
        union { __half h[4]; uint2 u; } U;
        U.h[0] = __float2half(v.x); U.h[1] = __float2half(v.y);
        U.h[2] = __float2half(v.z); U.h[3] = __float2half(v.w);
        *(uint2*)(Xf + (size_t)i * 4) = U.u;
    } else if (i < n1 + n2) {
        i -= n1;
        const float4 v = Wq[i];
        const float vv[4] = {v.x, v.y, v.z, v.w};
        union { __half h[4]; uint2 u; } H, L;
        #pragma unroll
        for (int k = 0; k < 4; k++) {
            __half hi = __float2half(vv[k]);
            H.h[k] = hi;
            L.h[k] = __float2half(vv[k] - __half2float(hi));
        }
        *(uint2*)(Wqh + (size_t)i * 4) = H.u;
        *(uint2*)(Wql + (size_t)i * 4) = L.u;
    } else if (i < n1 + n2 + n3) {
        i -= n1 + n2;
        const float4 v = Wo[i];
        union { __half h[4]; uint2 u; } U;
        U.h[0] = __float2half(v.x); U.h[1] = __float2half(v.y);
        U.h[2] = __float2half(v.z); U.h[3] = __float2half(v.w);
        *(uint2*)(Wof + (size_t)i * 4) = U.u;
    }
}

// ---------------------------------------------------------------------------
// Masked softmax; emits att single fp16. Vectorized.
// ---------------------------------------------------------------------------
__global__ void __launch_bounds__(256)
softmax_k(const float* __restrict__ att, const int* __restrict__ mask,
          __half* __restrict__ oh)
{
    const size_t row = blockIdx.x;
    const float4* a4 = (const float4*)(att  + row * (size_t)SLEN);
    const int4*   m4 = (const int4*)  (mask + row * (size_t)SLEN);
    const int tid = threadIdx.x;

    float v[8];
    const float4 x0 = a4[tid], x1 = a4[tid + 256];
    const int4   q0 = m4[tid], q1 = m4[tid + 256];
    v[0] = q0.x ? x0.x : -INFINITY;
    v[1] = q0.y ? x0.y : -INFINITY;
    v[2] = q0.z ? x0.z : -INFINITY;
    v[3] = q0.w ? x0.w : -INFINITY;
    v[4] = q1.x ? x1.x : -INFINITY;
    v[5] = q1.y ? x1.y : -INFINITY;
    v[6] = q1.z ? x1.z : -INFINITY;
    v[7] = q1.w ? x1.w : -INFINITY;

    float lmax = v[0];
    #pragma unroll
    for (int i = 1; i < 8; i++) lmax = fmaxf(lmax, v[i]);

    __shared__ float smax[8], ssum[8];
    #pragma unroll
    for (int o = 16; o > 0; o >>= 1)
        lmax = fmaxf(lmax, __shfl_xor_sync(0xffffffffu, lmax, o));
    if ((tid & 31) == 0) smax[tid >> 5] = lmax;
    __syncthreads();
    const float gmax = fmaxf(fmaxf(fmaxf(smax[0], smax[1]), fmaxf(smax[2], smax[3])),
                             fmaxf(fmaxf(smax[4], smax[5]), fmaxf(smax[6], smax[7])));
    float lsum = 0.0f;
    #pragma unroll
    for (int i = 0; i < 8; i++) { v[i] = __expf(v[i] - gmax); lsum += v[i]; }
    #pragma unroll
    for (int o = 16; o > 0; o >>= 1)
        lsum += __shfl_xor_sync(0xffffffffu, lsum, o);
    if ((tid & 31) == 0) ssum[tid >> 5] = lsum;
    __syncthreads();
    const float gsum = (ssum[0] + ssum[1]) + (ssum[2] + ssum[3])
                     + (ssum[4] + ssum[5]) + (ssum[6] + ssum[7]);
    const float inv = 1.0f / gsum;

    union { __half h[4]; uint2 u; } H0, H1;
    #pragma unroll
    for (int i = 0; i < 4; i++) H0.h[i] = __float2half(v[i] * inv);
    #pragma unroll
    for (int i = 0; i < 4; i++) H1.h[i] = __float2half(v[4 + i] * inv);
    const size_t base = row * (size_t)SLEN;
    *(uint2*)(oh + base + tid * 4)        = H0.u;
    *(uint2*)(oh + base + 1024 + tid * 4) = H1.u;
}

// ---------------------------------------------------------------------------
extern "C" void kernel_launch(void* const* d_in, const int* in_sizes, int n_in,
                              void* d_out, int out_size)
{
    const float* X     = (const float*)d_in[0];
    const int*   mask  = (const int*)  d_in[1];
    const float* W_qkv = (const float*)d_in[2];
    const float* b_qkv = (const float*)d_in[3];
    const float* W_out = (const float*)d_in[4];
    const float* b_out = (const float*)d_in[5];
    float*       out   = (float*)d_out;

    __half *Xf, *Wqh, *Wql, *Wof, *qf, *kf, *vtf, *athf, *cfh, *cfl;
    float *att;
    cudaGetSymbolAddress((void**)&Xf,   g_Xf);
    cudaGetSymbolAddress((void**)&Wqh,  g_Wqh);  cudaGetSymbolAddress((void**)&Wql,  g_Wql);
    cudaGetSymbolAddress((void**)&Wof,  g_Wof);
    cudaGetSymbolAddress((void**)&qf,   g_qf);
    cudaGetSymbolAddress((void**)&kf,   g_kf);
    cudaGetSymbolAddress((void**)&vtf,  g_vtf);
    cudaGetSymbolAddress((void**)&att,  g_att);
    cudaGetSymbolAddress((void**)&athf, g_athf);
    cudaGetSymbolAddress((void**)&cfh,  g_cfh);  cudaGetSymbolAddress((void**)&cfl,  g_cfl);

    cudaFuncSetAttribute(hgemm_k<0>, cudaFuncAttributeMaxDynamicSharedMemorySize, HG_SMEM3);
    cudaFuncSetAttribute(hgemm_k<1>, cudaFuncAttributeMaxDynamicSharedMemorySize, HG_SMEM2);
    cudaFuncSetAttribute(hgemm_k<2>, cudaFuncAttributeMaxDynamicSharedMemorySize, HG_SMEM2);
    cudaFuncSetAttribute(hgemm_k<3>, cudaFuncAttributeMaxDynamicSharedMemorySize, HG_SMEM3);

    // Convert inputs (single launch)
    {
        const int n1 = BATCH*SLEN*EMB/4, n2 = QKVF*EMB/4, n3 = EMB*EMB/4;
        conv_all<<<(n1 + n2 + n3 + 255)/256, 256>>>(
            (const float4*)X, Xf, n1,
            (const float4*)W_qkv, Wqh, Wql, n2,
            (const float4*)W_out, Wof, n3);
    }

    // 1) qkv = X @ W_qkv^T + b — X single, Wq split -> q fp16, k fp16, V^T fp16
    hgemm_k<0><<<dim3(QKVF/128, (BATCH*SLEN)/128), 256, HG_SMEM3>>>(
        Wqh, Wql, Xf,
        0, EMB, 0, EMB, EMB, 1.0f,
        nullptr, 0, 0, qf, kf, vtf, b_qkv);

    // 2) att = (Q @ K^T) / 32 — pure fp16 (fp32 out, per batch)
    hgemm_k<1><<<dim3(SLEN/128, SLEN/128, BATCH), 256, HG_SMEM2>>>(
        kf, nullptr, qf,
        (size_t)SLEN*EMB, EMB, (size_t)SLEN*EMB, EMB, EMB, 0.03125f,
        att, (size_t)SLEN*SLEN, SLEN, nullptr, nullptr, nullptr, nullptr);

    // 3) masked softmax -> att single fp16
    softmax_k<<<BATCH*SLEN, 256>>>(att, mask, athf);

    // 4) ctx = att @ V — pure fp16 -> ctx fp16 hi/lo
    hgemm_k<2><<<dim3(EMB/128, SLEN/128, BATCH), 256, HG_SMEM2>>>(
        vtf, nullptr, athf,
        (size_t)EMB*SLEN, SLEN, (size_t)SLEN*SLEN, SLEN, SLEN, 1.0f,
        nullptr, 0, 0, cfh, cfl, nullptr, nullptr);

    // 5) out = ctx @ W_out^T + b — ctx split, W_out single (fp32 out)
    hgemm_k<3><<<dim3(EMB/128, (BATCH*SLEN)/128), 256, HG_SMEM3>>>(
        cfh, cfl, Wof,
        0, EMB, 0, EMB, EMB, 1.0f,
        out, 0, EMB, nullptr, nullptr, nullptr, b_out);
}

// round 14
// speedup vs baseline: 1.2782x; 1.2782x over previous
#include <cuda_runtime.h>
#include <cuda_fp16.h>
#include <math.h>
#include <stdint.h>

// Problem constants
#define BATCH 4
#define SLEN  2048
#define EMB   1024
#define QKVF  3072

// ---------------------------------------------------------------------------
// Device scratch (allocation-free rule: __device__ globals)
// ---------------------------------------------------------------------------
__device__ __align__(256) __half g_Xf [(size_t)BATCH*SLEN*EMB];   // X fp16
__device__ __align__(256) __half g_Wqf[(size_t)QKVF*EMB];         // W_qkv fp16
__device__ __align__(256) __half g_Wof[(size_t)EMB*EMB];          // W_out fp16
__device__ __align__(256) __half g_qf [(size_t)BATCH*SLEN*EMB];   // q fp16
__device__ __align__(256) __half g_kf [(size_t)BATCH*SLEN*EMB];   // k fp16
__device__ __align__(256) __half g_vtf[(size_t)BATCH*EMB*SLEN];   // V^T fp16 [b,e,s]
__device__ __align__(256) float  g_att[(size_t)BATCH*SLEN*SLEN];
__device__ __align__(256) __half g_athf[(size_t)BATCH*SLEN*SLEN]; // att fp16
__device__ __align__(256) __half g_cf [(size_t)BATCH*SLEN*EMB];   // ctx fp16

// ---------------------------------------------------------------------------
// PTX helpers (sm_80+ only — tcgen05 rejected by compute_103 PTX target)
// ---------------------------------------------------------------------------
__device__ __forceinline__ uint32_t smem_u32(const void* p) {
    uint32_t a;
    asm("{ .reg .u64 t; cvta.to.shared.u64 t, %1; cvt.u32.u64 %0, t; }"
        : "=r"(a) : "l"(p));
    return a;
}
#define CP16(d, s)   asm volatile("cp.async.cg.shared.global [%0], [%1], 16;" :: "r"(d), "l"(s))
#define CP_COMMIT()  asm volatile("cp.async.commit_group;" ::: "memory")
#define CP_WAIT0()   asm volatile("cp.async.wait_group 0;" ::: "memory")

__device__ __forceinline__ void ldsm4(uint32_t* r, uint32_t addr) {
    asm volatile("ldmatrix.sync.aligned.m8n8.x4.shared.b16 {%0,%1,%2,%3}, [%4];"
        : "=r"(r[0]), "=r"(r[1]), "=r"(r[2]), "=r"(r[3]) : "r"(addr));
}
__device__ __forceinline__ void hmma16816(float* d, const uint32_t* a, const uint32_t* b) {
    asm volatile("mma.sync.aligned.m16n8k16.row.col.f32.f16.f16.f32 "
        "{%0,%1,%2,%3}, {%4,%5,%6,%7}, {%8,%9}, {%0,%1,%2,%3};"
        : "+f"(d[0]), "+f"(d[1]), "+f"(d[2]), "+f"(d[3])
        : "r"(a[0]), "r"(a[1]), "r"(a[2]), "r"(a[3]), "r"(b[0]), "r"(b[1]));
}

// ---- pure fp16 tiling: CTA 128x128, BK=64, 8 warps (2x4), 2 CTAs/SM ----
#define HROWB   144
#define HTILE   (128 * HROWB)            // 18432 B
#define HSTAGE  (2 * HTILE)              // B tile + A tile
#define HG_SMEM (2 * HSTAGE + 128)       // 73856 B

// ===========================================================================
// hgemm (pure fp16, 1 MMA):  D[m,n] = alpha*sum_k A[m,k]B[n,k] (+bias)
// MODE 0 (qkv):    A=X, B=Wq; bias; emit q fp16 / k fp16 / V^T fp16 (transposed)
// MODE 1 (scores): A=q, B=k; fp32 att out (batched)
// MODE 2 (ctx):    A=att, B=V^T; ctx fp16 out (batched)
// MODE 3 (proj):   A=ctx, B=Wo; bias; fp32 out
// ===========================================================================
template<int MODE>
__global__ void __launch_bounds__(256, 2)
hgemm_k(const __half* __restrict__ A, const __half* __restrict__ B,
        size_t sA, int ldA, size_t sB, int ldB, int K, float alpha,
        float* __restrict__ outF, size_t sF, int ldF,
        __half* __restrict__ o0, __half* __restrict__ o1,
        __half* __restrict__ o3,
        const float* __restrict__ bias)
{
    extern __shared__ char dsm[];
    const uint32_t sb0 = smem_u32(dsm);
    const uint32_t SB  = (sb0 + 127u) & ~127u;
    float* stg = (float*)(dsm + (SB - sb0));

    const int tid  = threadIdx.x;
    const int wid  = tid >> 5, lane = tid & 31;
    const int wm   = wid >> 2, wn = wid & 3;    // warp 64x32
    const int bx = blockIdx.x, by = blockIdx.y, z = blockIdx.z;

    const char* bB = (const char*)(B + (size_t)z * sB + (size_t)bx * 128 * ldB);
    const char* bA = (const char*)(A + (size_t)z * sA + (size_t)by * 128 * ldA);
    const size_t strB = (size_t)ldB * 2, strA = (size_t)ldA * 2;

    auto load_chunk = [&](int c, int s) {
        const uint32_t stb = SB + (uint32_t)s * HSTAGE;
        #pragma unroll
        for (int i = 0; i < 8; i++) {
            const int id = i * 256 + tid;       // 0..2047
            const int t  = id >> 10;            // 0 = B tile, 1 = A tile
            const int u  = id & 1023;
            const int r  = u >> 3;
            const int c16 = u & 7;
            const char* base = t ? bA : bB;
            const size_t str = t ? strA : strB;
            const char* src = base + (size_t)r * str + (size_t)c * 128 + (size_t)c16 * 16;
            const uint32_t dst = stb + (uint32_t)t * HTILE + (uint32_t)(r * HROWB + c16 * 16);
            CP16(dst, src);
        }
        CP_COMMIT();
    };

    float d[4][4][4];
    #pragma unroll
    for (int a = 0; a < 4; a++)
        #pragma unroll
        for (int b = 0; b < 4; b++)
            #pragma unroll
            for (int e = 0; e < 4; e++) d[a][b][e] = 0.0f;

    const int NC = K >> 6;
    load_chunk(0, 0);

    const uint32_t offA = (uint32_t)((wm * 64 + (lane & 7) + ((lane >> 3) & 1) * 8) * HROWB
                                     + ((lane >> 4) & 1) * 16);
    const uint32_t offB = (uint32_t)((wn * 32 + ((lane >> 4) & 1) * 8 + (lane & 7)) * HROWB
                                     + ((lane >> 3) & 1) * 16);

    for (int c = 0; c < NC; c++) {
        CP_WAIT0();
        __syncthreads();
        const int s = c & 1;
        if (c + 1 < NC) load_chunk(c + 1, s ^ 1);

        const uint32_t stb = SB + (uint32_t)s * HSTAGE;
        const uint32_t B_s = stb, A_s = stb + HTILE;

        #pragma unroll
        for (int kk = 0; kk < 4; kk++) {
            uint32_t bq[8];
            ldsm4(&bq[0], B_s + offB + (uint32_t)(kk * 32));
            ldsm4(&bq[4], B_s + offB + (uint32_t)(16 * HROWB + kk * 32));
            #pragma unroll
            for (int mt = 0; mt < 4; mt++) {
                uint32_t a[4];
                ldsm4(a, A_s + offA + (uint32_t)(mt * 16 * HROWB + kk * 32));
                #pragma unroll
                for (int nt = 0; nt < 4; nt++)
                    hmma16816(d[mt][nt], a, &bq[nt * 2]);
            }
        }
    }
    __syncthreads();

    // ---- accumulators -> smem staging (alpha, optional bias) ----
    #pragma unroll
    for (int mt = 0; mt < 4; mt++) {
        #pragma unroll
        for (int nt = 0; nt < 4; nt++) {
            const int r0 = wm * 64 + mt * 16 + (lane >> 2);
            const int c0 = wn * 32 + nt * 8 + (lane & 3) * 2;
            #pragma unroll
            for (int h = 0; h < 2; h++) {
                float v0 = d[mt][nt][h * 2 + 0] * alpha;
                float v1 = d[mt][nt][h * 2 + 1] * alpha;
                if (MODE == 0 || MODE == 3) {
                    v0 += bias[bx * 128 + c0];
                    v1 += bias[bx * 128 + c0 + 1];
                }
                *(float2*)&stg[(r0 + h * 8) * 132 + c0] = make_float2(v0, v1);
            }
        }
    }
    __syncthreads();

    // ---- MODE-specific writers ----
    if (MODE == 1 || MODE == 3) {
        const int row = tid >> 1, h = tid & 1;
        float* dst = outF + (size_t)z * sF + ((size_t)by * 128 + row) * ldF
                   + (size_t)bx * 128 + h * 64;
        #pragma unroll
        for (int q = 0; q < 16; q++) {
            float4 v;
            v.x = stg[row * 132 + h * 64 + q * 4 + 0];
            v.y = stg[row * 132 + h * 64 + q * 4 + 1];
            v.z = stg[row * 132 + h * 64 + q * 4 + 2];
            v.w = stg[row * 132 + h * 64 + q * 4 + 3];
            ((float4*)dst)[q] = v;
        }
    } else if (MODE == 2) {
        // ctx -> single fp16 (row-major), o0
        #pragma unroll 1
        for (int cb = 0; cb < 4; cb++) {
            #pragma unroll 1
            for (int it = 0; it < 2; it++) {
                const int row = it * 64 + (tid >> 2);
                const int qq  = tid & 3;
                const int col = cb * 32 + qq * 8;
                const size_t rg = (size_t)z * SLEN + (size_t)by * 128 + row;
                union { __half h[8]; uint4 v; } U;
                #pragma unroll
                for (int i = 0; i < 8; i++)
                    U.h[i] = __float2half(stg[row * 132 + col + i]);
                *(uint4*)(o0 + rg * 1024 + bx * 128 + col) = U.v;
            }
        }
    } else if (MODE == 0 && bx < 16) {      // q (bx<8 -> o0) / k (bx<16 -> o1)
        __half* O = (bx < 8) ? o0 : o1;
        const int cbase = (bx & 7) * 128;
        #pragma unroll 1
        for (int cb = 0; cb < 4; cb++) {
            #pragma unroll 1
            for (int it = 0; it < 2; it++) {
                const int row = it * 64 + (tid >> 2);
                const int qq  = tid & 3;
                const int col = cb * 32 + qq * 8;
                const size_t rg = (size_t)by * 128 + row;
                union { __half h[8]; uint4 v; } U;
                #pragma unroll
                for (int i = 0; i < 8; i++)
                    U.h[i] = __float2half(stg[row * 132 + col + i]);
                *(uint4*)(O + rg * 1024 + cbase + col) = U.v;
            }
        }
    } else if (MODE == 0) {                 // V^T fp16, transposed (o3)
        const int j  = tid >> 3;
        const int rs = tid & 7;
        const int bidx = by >> 4;
        const int s0 = (by * 128) & 2047;
        #pragma unroll 1
        for (int cb = 0; cb < 4; cb++) {
            const int col = cb * 32 + j;
            const int colE = (bx - 16) * 128 + col;
            union { __half h[16]; uint4 v[2]; } U;
            #pragma unroll
            for (int i = 0; i < 16; i++)
                U.h[i] = __float2half(stg[(rs * 16 + i) * 132 + col]);
            const size_t off = ((size_t)bidx * 1024 + colE) * 2048 + s0 + rs * 16;
            *(uint4*)(o3 + off)     = U.v[0];
            *(uint4*)(o3 + off + 8) = U.v[1];
        }
    }
}

// ---------------------------------------------------------------------------
// Input conversion: X, W_qkv, W_out -> single fp16, ONE launch
// ---------------------------------------------------------------------------
__global__ void conv_all(const float4* __restrict__ X,  __half* __restrict__ Xf, int n1,
                         const float4* __restrict__ Wq, __half* __restrict__ Wqf, int n2,
                         const float4* __restrict__ Wo, __half* __restrict__ Wof, int n3)
{
    int i = blockIdx.x * 256 + threadIdx.x;
    const float4* src; __half* dst;
    if (i < n1)            { src = X;  dst = Xf;  }
    else if (i < n1 + n2)  { src = Wq; dst = Wqf; i -= n1; }
    else if (i < n1+n2+n3) { src = Wo; dst = Wof; i -= n1 + n2; }
    else return;
    const float4 v = src[i];
    union { __half h[4]; uint2 u; } U;
    U.h[0] = __float2half(v.x); U.h[1] = __float2half(v.y);
    U.h[2] = __float2half(v.z); U.h[3] = __float2half(v.w);
    *(uint2*)(dst + (size_t)i * 4) = U.u;
}

// ---------------------------------------------------------------------------
// Masked softmax; emits att single fp16. Vectorized.
// ---------------------------------------------------------------------------
__global__ void __launch_bounds__(256)
softmax_k(const float* __restrict__ att, const int* __restrict__ mask,
          __half* __restrict__ oh)
{
    const size_t row = blockIdx.x;
    const float4* a4 = (const float4*)(att  + row * (size_t)SLEN);
    const int4*   m4 = (const int4*)  (mask + row * (size_t)SLEN);
    const int tid = threadIdx.x;

    float v[8];
    const float4 x0 = a4[tid], x1 = a4[tid + 256];
    const int4   q0 = m4[tid], q1 = m4[tid + 256];
    v[0] = q0.x ? x0.x : -INFINITY;
    v[1] = q0.y ? x0.y : -INFINITY;
    v[2] = q0.z ? x0.z : -INFINITY;
    v[3] = q0.w ? x0.w : -INFINITY;
    v[4] = q1.x ? x1.x : -INFINITY;
    v[5] = q1.y ? x1.y : -INFINITY;
    v[6] = q1.z ? x1.z : -INFINITY;
    v[7] = q1.w ? x1.w : -INFINITY;

    float lmax = v[0];
    #pragma unroll
    for (int i = 1; i < 8; i++) lmax = fmaxf(lmax, v[i]);

    __shared__ float smax[8], ssum[8];
    #pragma unroll
    for (int o = 16; o > 0; o >>= 1)
        lmax = fmaxf(lmax, __shfl_xor_sync(0xffffffffu, lmax, o));
    if ((tid & 31) == 0) smax[tid >> 5] = lmax;
    __syncthreads();
    const float gmax = fmaxf(fmaxf(fmaxf(smax[0], smax[1]), fmaxf(smax[2], smax[3])),
                             fmaxf(fmaxf(smax[4], smax[5]), fmaxf(smax[6], smax[7])));
    float lsum = 0.0f;
    #pragma unroll
    for (int i = 0; i < 8; i++) { v[i] = __expf(v[i] - gmax); lsum += v[i]; }
    #pragma unroll
    for (int o = 16; o > 0; o >>= 1)
        lsum += __shfl_xor_sync(0xffffffffu, lsum, o);
    if ((tid & 31) == 0) ssum[tid >> 5] = lsum;
    __syncthreads();
    const float gsum = (ssum[0] + ssum[1]) + (ssum[2] + ssum[3])
                     + (ssum[4] + ssum[5]) + (ssum[6] + ssum[7]);
    const float inv = 1.0f / gsum;

    union { __half h[4]; uint2 u; } H0, H1;
    #pragma unroll
    for (int i = 0; i < 4; i++) H0.h[i] = __float2half(v[i] * inv);
    #pragma unroll
    for (int i = 0; i < 4; i++) H1.h[i] = __float2half(v[4 + i] * inv);
    const size_t base = row * (size_t)SLEN;
    *(uint2*)(oh + base + tid * 4)        = H0.u;
    *(uint2*)(oh + base + 1024 + tid * 4) = H1.u;
}

// ---------------------------------------------------------------------------
extern "C" void kernel_launch(void* const* d_in, const int* in_sizes, int n_in,
                              void* d_out, int out_size)
{
    const float* X     = (const float*)d_in[0];
    const int*   mask  = (const int*)  d_in[1];
    const float* W_qkv = (const float*)d_in[2];
    const float* b_qkv = (const float*)d_in[3];
    const float* W_out = (const float*)d_in[4];
    const float* b_out = (const float*)d_in[5];
    float*       out   = (float*)d_out;

    __half *Xf, *Wqf, *Wof, *qf, *kf, *vtf, *athf, *cf;
    float *att;
    cudaGetSymbolAddress((void**)&Xf,   g_Xf);
    cudaGetSymbolAddress((void**)&Wqf,  g_Wqf);
    cudaGetSymbolAddress((void**)&Wof,  g_Wof);
    cudaGetSymbolAddress((void**)&qf,   g_qf);
    cudaGetSymbolAddress((void**)&kf,   g_kf);
    cudaGetSymbolAddress((void**)&vtf,  g_vtf);
    cudaGetSymbolAddress((void**)&att,  g_att);
    cudaGetSymbolAddress((void**)&athf, g_athf);
    cudaGetSymbolAddress((void**)&cf,   g_cf);

    cudaFuncSetAttribute(hgemm_k<0>, cudaFuncAttributeMaxDynamicSharedMemorySize, HG_SMEM);
    cudaFuncSetAttribute(hgemm_k<1>, cudaFuncAttributeMaxDynamicSharedMemorySize, HG_SMEM);
    cudaFuncSetAttribute(hgemm_k<2>, cudaFuncAttributeMaxDynamicSharedMemorySize, HG_SMEM);
    cudaFuncSetAttribute(hgemm_k<3>, cudaFuncAttributeMaxDynamicSharedMemorySize, HG_SMEM);

    // Convert inputs (single launch)
    {
        const int n1 = BATCH*SLEN*EMB/4, n2 = QKVF*EMB/4, n3 = EMB*EMB/4;
        conv_all<<<(n1 + n2 + n3 + 255)/256, 256>>>(
            (const float4*)X, Xf, n1,
            (const float4*)W_qkv, Wqf, n2,
            (const float4*)W_out, Wof, n3);
    }

    // 1) qkv = X @ W_qkv^T + b  -> q fp16, k fp16, V^T fp16
    hgemm_k<0><<<dim3(QKVF/128, (BATCH*SLEN)/128), 256, HG_SMEM>>>(
        Xf, Wqf, 0, EMB, 0, EMB, EMB, 1.0f,
        nullptr, 0, 0, qf, kf, vtf, b_qkv);

    // 2) att = (Q @ K^T) / 32   (fp32 out, per batch)
    hgemm_k<1><<<dim3(SLEN/128, SLEN/128, BATCH), 256, HG_SMEM>>>(
        qf, kf, (size_t)SLEN*EMB, EMB, (size_t)SLEN*EMB, EMB, EMB, 0.03125f,
        att, (size_t)SLEN*SLEN, SLEN, nullptr, nullptr, nullptr, nullptr);

    // 3) masked softmax -> att single fp16
    softmax_k<<<BATCH*SLEN, 256>>>(att, mask, athf);

    // 4) ctx = att @ V  (B = V^T)  -> ctx fp16
    hgemm_k<2><<<dim3(EMB/128, SLEN/128, BATCH), 256, HG_SMEM>>>(
        athf, vtf, (size_t)SLEN*SLEN, SLEN, (size_t)EMB*SLEN, SLEN, SLEN, 1.0f,
        nullptr, 0, 0, cf, nullptr, nullptr, nullptr);

    // 5) out = ctx @ W_out^T + b  (fp32 out)
    hgemm_k<3><<<dim3(EMB/128, (BATCH*SLEN)/128), 256, HG_SMEM>>>(
        cf, Wof, 0, EMB, 0, EMB, EMB, 1.0f,
        out, 0, EMB, nullptr, nullptr, nullptr, b_out);
}

// round 15
// speedup vs baseline: 1.3100x; 1.0249x over previous
#include <cuda_runtime.h>
#include <cuda_fp16.h>
#include <math.h>
#include <stdint.h>

// Problem constants
#define BATCH 4
#define SLEN  2048
#define EMB   1024
#define QKVF  3072

// ---------------------------------------------------------------------------
// Device scratch (allocation-free rule: __device__ globals)
// ---------------------------------------------------------------------------
__device__ __align__(256) __half g_Xf [(size_t)BATCH*SLEN*EMB];   // X fp16
__device__ __align__(256) __half g_Wqf[(size_t)QKVF*EMB];         // W_qkv fp16
__device__ __align__(256) __half g_Wof[(size_t)EMB*EMB];          // W_out fp16
__device__ __align__(256) __half g_qf [(size_t)BATCH*SLEN*EMB];   // q fp16
__device__ __align__(256) __half g_kf [(size_t)BATCH*SLEN*EMB];   // k fp16
__device__ __align__(256) __half g_vtf[(size_t)BATCH*EMB*SLEN];   // V^T fp16 [b,e,s]
__device__ __align__(256) float  g_att[(size_t)BATCH*SLEN*SLEN];
__device__ __align__(256) __half g_athf[(size_t)BATCH*SLEN*SLEN]; // att fp16
__device__ __align__(256) __half g_cf [(size_t)BATCH*SLEN*EMB];   // ctx fp16

// ---------------------------------------------------------------------------
// PTX helpers (sm_80+ only — tcgen05 rejected by compute_103 PTX target)
// ---------------------------------------------------------------------------
__device__ __forceinline__ uint32_t smem_u32(const void* p) {
    uint32_t a;
    asm("{ .reg .u64 t; cvta.to.shared.u64 t, %1; cvt.u32.u64 %0, t; }"
        : "=r"(a) : "l"(p));
    return a;
}
#define CP16(d, s)   asm volatile("cp.async.cg.shared.global [%0], [%1], 16;" :: "r"(d), "l"(s))
#define CP_COMMIT()  asm volatile("cp.async.commit_group;" ::: "memory")
#define CP_WAIT1()   asm volatile("cp.async.wait_group 1;" ::: "memory")
#define CP_WAIT0()   asm volatile("cp.async.wait_group 0;" ::: "memory")

__device__ __forceinline__ void ldsm4(uint32_t* r, uint32_t addr) {
    asm volatile("ldmatrix.sync.aligned.m8n8.x4.shared.b16 {%0,%1,%2,%3}, [%4];"
        : "=r"(r[0]), "=r"(r[1]), "=r"(r[2]), "=r"(r[3]) : "r"(addr));
}
__device__ __forceinline__ void hmma16816(float* d, const uint32_t* a, const uint32_t* b) {
    asm volatile("mma.sync.aligned.m16n8k16.row.col.f32.f16.f16.f32 "
        "{%0,%1,%2,%3}, {%4,%5,%6,%7}, {%8,%9}, {%0,%1,%2,%3};"
        : "+f"(d[0]), "+f"(d[1]), "+f"(d[2]), "+f"(d[3])
        : "r"(a[0]), "r"(a[1]), "r"(a[2]), "r"(a[3]), "r"(b[0]), "r"(b[1]));
}

// ---- pure fp16 tiling: CTA 128x128, BK=64, 8 warps (2x4), 2 CTAs/SM ----
// 3-stage cp.async pipeline (2 loads in flight).
#define HROWB   144
#define HTILE   (128 * HROWB)            // 18432 B
#define HSTAGE  (2 * HTILE)              // B tile + A tile = 36864 B
#define NSTAGES 3
#define HG_SMEM (NSTAGES * HSTAGE + 128) // 110720 B -> 2 CTAs/SM

// ===========================================================================
// hgemm (pure fp16, 1 MMA):  D[m,n] = alpha*sum_k A[m,k]B[n,k] (+bias)
// MODE 0 (qkv):    A=X, B=Wq; bias; emit q fp16 / k fp16 / V^T fp16 (transposed)
// MODE 1 (scores): A=q, B=k; fp32 att out (batched)
// MODE 2 (ctx):    A=att, B=V^T; ctx fp16 out (batched)
// MODE 3 (proj):   A=ctx, B=Wo; bias; fp32 out
// ===========================================================================
template<int MODE>
__global__ void __launch_bounds__(256, 2)
hgemm_k(const __half* __restrict__ A, const __half* __restrict__ B,
        size_t sA, int ldA, size_t sB, int ldB, int K, float alpha,
        float* __restrict__ outF, size_t sF, int ldF,
        __half* __restrict__ o0, __half* __restrict__ o1,
        __half* __restrict__ o3,
        const float* __restrict__ bias)
{
    extern __shared__ char dsm[];
    const uint32_t sb0 = smem_u32(dsm);
    const uint32_t SB  = (sb0 + 127u) & ~127u;
    float* stg = (float*)(dsm + (SB - sb0));

    const int tid  = threadIdx.x;
    const int wid  = tid >> 5, lane = tid & 31;
    const int wm   = wid >> 2, wn = wid & 3;    // warp 64x32
    const int bx = blockIdx.x, by = blockIdx.y, z = blockIdx.z;

    const char* bB = (const char*)(B + (size_t)z * sB + (size_t)bx * 128 * ldB);
    const char* bA = (const char*)(A + (size_t)z * sA + (size_t)by * 128 * ldA);
    const size_t strB = (size_t)ldB * 2, strA = (size_t)ldA * 2;

    auto load_chunk = [&](int c, int s) {
        const uint32_t stb = SB + (uint32_t)s * HSTAGE;
        #pragma unroll
        for (int i = 0; i < 8; i++) {
            const int id = i * 256 + tid;       // 0..2047
            const int t  = id >> 10;            // 0 = B tile, 1 = A tile
            const int u  = id & 1023;
            const int r  = u >> 3;
            const int c16 = u & 7;
            const char* base = t ? bA : bB;
            const size_t str = t ? strA : strB;
            const char* src = base + (size_t)r * str + (size_t)c * 128 + (size_t)c16 * 16;
            const uint32_t dst = stb + (uint32_t)t * HTILE + (uint32_t)(r * HROWB + c16 * 16);
            CP16(dst, src);
        }
        CP_COMMIT();
    };

    float d[4][4][4];
    #pragma unroll
    for (int a = 0; a < 4; a++)
        #pragma unroll
        for (int b = 0; b < 4; b++)
            #pragma unroll
            for (int e = 0; e < 4; e++) d[a][b][e] = 0.0f;

    const int NC = K >> 6;
    // Prologue: two chunks in flight
    load_chunk(0, 0);
    if (NC > 1) load_chunk(1, 1);

    const uint32_t offA = (uint32_t)((wm * 64 + (lane & 7) + ((lane >> 3) & 1) * 8) * HROWB
                                     + ((lane >> 4) & 1) * 16);
    const uint32_t offB = (uint32_t)((wn * 32 + ((lane >> 4) & 1) * 8 + (lane & 7)) * HROWB
                                     + ((lane >> 3) & 1) * 16);

    int stage = 0;
    for (int c = 0; c < NC; c++) {
        if (c + 1 < NC) CP_WAIT1(); else CP_WAIT0();
        __syncthreads();
        // Issue chunk c+2 into the stage just freed by chunk c-1.
        if (c + 2 < NC) {
            int s2 = stage + 2; if (s2 >= NSTAGES) s2 -= NSTAGES;
            load_chunk(c + 2, s2);
        }

        const uint32_t stb = SB + (uint32_t)stage * HSTAGE;
        const uint32_t B_s = stb, A_s = stb + HTILE;

        #pragma unroll
        for (int kk = 0; kk < 4; kk++) {
            uint32_t bq[8];
            ldsm4(&bq[0], B_s + offB + (uint32_t)(kk * 32));
            ldsm4(&bq[4], B_s + offB + (uint32_t)(16 * HROWB + kk * 32));
            #pragma unroll
            for (int mt = 0; mt < 4; mt++) {
                uint32_t a[4];
                ldsm4(a, A_s + offA + (uint32_t)(mt * 16 * HROWB + kk * 32));
                #pragma unroll
                for (int nt = 0; nt < 4; nt++)
                    hmma16816(d[mt][nt], a, &bq[nt * 2]);
            }
        }
        if (++stage == NSTAGES) stage = 0;
    }
    __syncthreads();

    // ---- accumulators -> smem staging (alpha, optional bias) ----
    #pragma unroll
    for (int mt = 0; mt < 4; mt++) {
        #pragma unroll
        for (int nt = 0; nt < 4; nt++) {
            const int r0 = wm * 64 + mt * 16 + (lane >> 2);
            const int c0 = wn * 32 + nt * 8 + (lane & 3) * 2;
            #pragma unroll
            for (int h = 0; h < 2; h++) {
                float v0 = d[mt][nt][h * 2 + 0] * alpha;
                float v1 = d[mt][nt][h * 2 + 1] * alpha;
                if (MODE == 0 || MODE == 3) {
                    v0 += bias[bx * 128 + c0];
                    v1 += bias[bx * 128 + c0 + 1];
                }
                *(float2*)&stg[(r0 + h * 8) * 132 + c0] = make_float2(v0, v1);
            }
        }
    }
    __syncthreads();

    // ---- MODE-specific writers ----
    if (MODE == 1 || MODE == 3) {
        const int row = tid >> 1, h = tid & 1;
        float* dst = outF + (size_t)z * sF + ((size_t)by * 128 + row) * ldF
                   + (size_t)bx * 128 + h * 64;
        #pragma unroll
        for (int q = 0; q < 16; q++) {
            float4 v;
            v.x = stg[row * 132 + h * 64 + q * 4 + 0];
            v.y = stg[row * 132 + h * 64 + q * 4 + 1];
            v.z = stg[row * 132 + h * 64 + q * 4 + 2];
            v.w = stg[row * 132 + h * 64 + q * 4 + 3];
            ((float4*)dst)[q] = v;
        }
    } else if (MODE == 2) {
        // ctx -> single fp16 (row-major), o0
        #pragma unroll 1
        for (int cb = 0; cb < 4; cb++) {
            #pragma unroll 1
            for (int it = 0; it < 2; it++) {
                const int row = it * 64 + (tid >> 2);
                const int qq  = tid & 3;
                const int col = cb * 32 + qq * 8;
                const size_t rg = (size_t)z * SLEN + (size_t)by * 128 + row;
                union { __half h[8]; uint4 v; } U;
                #pragma unroll
                for (int i = 0; i < 8; i++)
                    U.h[i] = __float2half(stg[row * 132 + col + i]);
                *(uint4*)(o0 + rg * 1024 + bx * 128 + col) = U.v;
            }
        }
    } else if (MODE == 0 && bx < 16) {      // q (bx<8 -> o0) / k (bx<16 -> o1)
        __half* O = (bx < 8) ? o0 : o1;
        const int cbase = (bx & 7) * 128;
        #pragma unroll 1
        for (int cb = 0; cb < 4; cb++) {
            #pragma unroll 1
            for (int it = 0; it < 2; it++) {
                const int row = it * 64 + (tid >> 2);
                const int qq  = tid & 3;
                const int col = cb * 32 + qq * 8;
                const size_t rg = (size_t)by * 128 + row;
                union { __half h[8]; uint4 v; } U;
                #pragma unroll
                for (int i = 0; i < 8; i++)
                    U.h[i] = __float2half(stg[row * 132 + col + i]);
                *(uint4*)(O + rg * 1024 + cbase + col) = U.v;
            }
        }
    } else if (MODE == 0) {                 // V^T fp16, transposed (o3)
        const int j  = tid >> 3;
        const int rs = tid & 7;
        const int bidx = by >> 4;
        const int s0 = (by * 128) & 2047;
        #pragma unroll 1
        for (int cb = 0; cb < 4; cb++) {
            const int col = cb * 32 + j;
            const int colE = (bx - 16) * 128 + col;
            union { __half h[16]; uint4 v[2]; } U;
            #pragma unroll
            for (int i = 0; i < 16; i++)
                U.h[i] = __float2half(stg[(rs * 16 + i) * 132 + col]);
            const size_t off = ((size_t)bidx * 1024 + colE) * 2048 + s0 + rs * 16;
            *(uint4*)(o3 + off)     = U.v[0];
            *(uint4*)(o3 + off + 8) = U.v[1];
        }
    }
}

// ---------------------------------------------------------------------------
// Input conversion: X, W_qkv, W_out -> single fp16, ONE launch
// ---------------------------------------------------------------------------
__global__ void conv_all(const float4* __restrict__ X,  __half* __restrict__ Xf, int n1,
                         const float4* __restrict__ Wq, __half* __restrict__ Wqf, int n2,
                         const float4* __restrict__ Wo, __half* __restrict__ Wof, int n3)
{
    int i = blockIdx.x * 256 + threadIdx.x;
    const float4* src; __half* dst;
    if (i < n1)            { src = X;  dst = Xf;  }
    else if (i < n1 + n2)  { src = Wq; dst = Wqf; i -= n1; }
    else if (i < n1+n2+n3) { src = Wo; dst = Wof; i -= n1 + n2; }
    else return;
    const float4 v = src[i];
    union { __half h[4]; uint2 u; } U;
    U.h[0] = __float2half(v.x); U.h[1] = __float2half(v.y);
    U.h[2] = __float2half(v.z); U.h[3] = __float2half(v.w);
    *(uint2*)(dst + (size_t)i * 4) = U.u;
}

// ---------------------------------------------------------------------------
// Masked softmax; emits att single fp16. Vectorized.
// ---------------------------------------------------------------------------
__global__ void __launch_bounds__(256)
softmax_k(const float* __restrict__ att, const int* __restrict__ mask,
          __half* __restrict__ oh)
{
    const size_t row = blockIdx.x;
    const float4* a4 = (const float4*)(att  + row * (size_t)SLEN);
    const int4*   m4 = (const int4*)  (mask + row * (size_t)SLEN);
    const int tid = threadIdx.x;

    float v[8];
    const float4 x0 = a4[tid], x1 = a4[tid + 256];
    const int4   q0 = m4[tid], q1 = m4[tid + 256];
    v[0] = q0.x ? x0.x : -INFINITY;
    v[1] = q0.y ? x0.y : -INFINITY;
    v[2] = q0.z ? x0.z : -INFINITY;
    v[3] = q0.w ? x0.w : -INFINITY;
    v[4] = q1.x ? x1.x : -INFINITY;
    v[5] = q1.y ? x1.y : -INFINITY;
    v[6] = q1.z ? x1.z : -INFINITY;
    v[7] = q1.w ? x1.w : -INFINITY;

    float lmax = v[0];
    #pragma unroll
    for (int i = 1; i < 8; i++) lmax = fmaxf(lmax, v[i]);

    __shared__ float smax[8], ssum[8];
    #pragma unroll
    for (int o = 16; o > 0; o >>= 1)
        lmax = fmaxf(lmax, __shfl_xor_sync(0xffffffffu, lmax, o));
    if ((tid & 31) == 0) smax[tid >> 5] = lmax;
    __syncthreads();
    const float gmax = fmaxf(fmaxf(fmaxf(smax[0], smax[1]), fmaxf(smax[2], smax[3])),
                             fmaxf(fmaxf(smax[4], smax[5]), fmaxf(smax[6], smax[7])));
    float lsum = 0.0f;
    #pragma unroll
    for (int i = 0; i < 8; i++) { v[i] = __expf(v[i] - gmax); lsum += v[i]; }
    #pragma unroll
    for (int o = 16; o > 0; o >>= 1)
        lsum += __shfl_xor_sync(0xffffffffu, lsum, o);
    if ((tid & 31) == 0) ssum[tid >> 5] = lsum;
    __syncthreads();
    const float gsum = (ssum[0] + ssum[1]) + (ssum[2] + ssum[3])
                     + (ssum[4] + ssum[5]) + (ssum[6] + ssum[7]);
    const float inv = 1.0f / gsum;

    union { __half h[4]; uint2 u; } H0, H1;
    #pragma unroll
    for (int i = 0; i < 4; i++) H0.h[i] = __float2half(v[i] * inv);
    #pragma unroll
    for (int i = 0; i < 4; i++) H1.h[i] = __float2half(v[4 + i] * inv);
    const size_t base = row * (size_t)SLEN;
    *(uint2*)(oh + base + tid * 4)        = H0.u;
    *(uint2*)(oh + base + 1024 + tid * 4) = H1.u;
}

// ---------------------------------------------------------------------------
extern "C" void kernel_launch(void* const* d_in, const int* in_sizes, int n_in,
                              void* d_out, int out_size)
{
    const float* X     = (const float*)d_in[0];
    const int*   mask  = (const int*)  d_in[1];
    const float* W_qkv = (const float*)d_in[2];
    const float* b_qkv = (const float*)d_in[3];
    const float* W_out = (const float*)d_in[4];
    const float* b_out = (const float*)d_in[5];
    float*       out   = (float*)d_out;

    __half *Xf, *Wqf, *Wof, *qf, *kf, *vtf, *athf, *cf;
    float *att;
    cudaGetSymbolAddress((void**)&Xf,   g_Xf);
    cudaGetSymbolAddress((void**)&Wqf,  g_Wqf);
    cudaGetSymbolAddress((void**)&Wof,  g_Wof);
    cudaGetSymbolAddress((void**)&qf,   g_qf);
    cudaGetSymbolAddress((void**)&kf,   g_kf);
    cudaGetSymbolAddress((void**)&vtf,  g_vtf);
    cudaGetSymbolAddress((void**)&att,  g_att);
    cudaGetSymbolAddress((void**)&athf, g_athf);
    cudaGetSymbolAddress((void**)&cf,   g_cf);

    cudaFuncSetAttribute(hgemm_k<0>, cudaFuncAttributeMaxDynamicSharedMemorySize, HG_SMEM);
    cudaFuncSetAttribute(hgemm_k<1>, cudaFuncAttributeMaxDynamicSharedMemorySize, HG_SMEM);
    cudaFuncSetAttribute(hgemm_k<2>, cudaFuncAttributeMaxDynamicSharedMemorySize, HG_SMEM);
    cudaFuncSetAttribute(hgemm_k<3>, cudaFuncAttributeMaxDynamicSharedMemorySize, HG_SMEM);

    // Convert inputs (single launch)
    {
        const int n1 = BATCH*SLEN*EMB/4, n2 = QKVF*EMB/4, n3 = EMB*EMB/4;
        conv_all<<<(n1 + n2 + n3 + 255)/256, 256>>>(
            (const float4*)X, Xf, n1,
            (const float4*)W_qkv, Wqf, n2,
            (const float4*)W_out, Wof, n3);
    }

    // 1) qkv = X @ W_qkv^T + b  -> q fp16, k fp16, V^T fp16
    hgemm_k<0><<<dim3(QKVF/128, (BATCH*SLEN)/128), 256, HG_SMEM>>>(
        Xf, Wqf, 0, EMB, 0, EMB, EMB, 1.0f,
        nullptr, 0, 0, qf, kf, vtf, b_qkv);

    // 2) att = (Q @ K^T) / 32   (fp32 out, per batch)
    hgemm_k<1><<<dim3(SLEN/128, SLEN/128, BATCH), 256, HG_SMEM>>>(
        qf, kf, (size_t)SLEN*EMB, EMB, (size_t)SLEN*EMB, EMB, EMB, 0.03125f,
        att, (size_t)SLEN*SLEN, SLEN, nullptr, nullptr, nullptr, nullptr);

    // 3) masked softmax -> att single fp16
    softmax_k<<<BATCH*SLEN, 256>>>(att, mask, athf);

    // 4) ctx = att @ V  (B = V^T)  -> ctx fp16
    hgemm_k<2><<<dim3(EMB/128, SLEN/128, BATCH), 256, HG_SMEM>>>(
        athf, vtf, (size_t)SLEN*SLEN, SLEN, (size_t)EMB*SLEN, SLEN, SLEN, 1.0f,
        nullptr, 0, 0, cf, nullptr, nullptr, nullptr);

    // 5) out = ctx @ W_out^T + b  (fp32 out)
    hgemm_k<3><<<dim3(EMB/128, (BATCH*SLEN)/128), 256, HG_SMEM>>>(
        cf, Wof, 0, EMB, 0, EMB, EMB, 1.0f,
        out, 0, EMB, nullptr, nullptr, nullptr, b_out);
}